// round 3
// baseline (speedup 1.0000x reference)
#include <cuda_runtime.h>

// SobelEdge3D: out = sqrt(ed^2 + eh^2 + ew^2 + 1e-6), separable Sobel.
// Round-3: packed f32x2 math (Blackwell) to halve element-wise FP issue count.
// Per plane p, per-thread (4 w positions, packed as 2 f32x2 lanes):
//   gw = x(w+1)-x(w-1), sw = x(w-1)+2x(w)+x(w+1)          (per row)
//   A = gw(h-1)+2gw(h)+gw(h+1); B = sw(h+1)-sw(h-1); C = sw(h-1)+2sw(h)+sw(h+1)
//   ed(t)=A(t-1)+2A(t)+A(t+1); eh(t) likewise from B; ew(t)=C(t+1)-C(t-1)

typedef unsigned long long u64;

constexpr int Wd  = 128;
constexpr int Hd  = 128;
constexpr int Dd  = 64;
constexpr int BCn = 32;          // B*C = 2*16
constexpr int HT  = 8;           // h rows per block (one warp per h row)
constexpr int ND  = 16;          // d outputs per block
constexpr int HW  = Hd * Wd;

__device__ __forceinline__ u64 pack2(float lo, float hi) {
    u64 r; asm("mov.b64 %0,{%1,%2};" : "=l"(r) : "f"(lo), "f"(hi)); return r;
}
__device__ __forceinline__ void unpack2(u64 v, float& lo, float& hi) {
    asm("mov.b64 {%0,%1},%2;" : "=f"(lo), "=f"(hi) : "l"(v));
}
__device__ __forceinline__ u64 add2(u64 a, u64 b) {
    u64 r; asm("add.rn.f32x2 %0,%1,%2;" : "=l"(r) : "l"(a), "l"(b)); return r;
}
__device__ __forceinline__ u64 mul2(u64 a, u64 b) {
    u64 r; asm("mul.rn.f32x2 %0,%1,%2;" : "=l"(r) : "l"(a), "l"(b)); return r;
}
__device__ __forceinline__ u64 fma2(u64 a, u64 b, u64 c) {
    u64 r; asm("fma.rn.f32x2 %0,%1,%2,%3;" : "=l"(r) : "l"(a), "l"(b), "l"(c)); return r;
}
__device__ __forceinline__ float rsqrtf_a(float v) {
    float r; asm("rsqrt.approx.f32 %0,%1;" : "=f"(r) : "f"(v)); return r;
}

struct ABC { u64 Al, Ah, Bl, Bh, Cl, Ch; };

__global__ __launch_bounds__(256, 2)
void sobel3d_kernel(const float* __restrict__ x, float* __restrict__ out)
{
    const int tx = threadIdx.x;                 // 0..31 -> w = 4*tx..4*tx+3
    const int ty = threadIdx.y;                 // 0..7  -> h row (warp-uniform)
    const int h0 = blockIdx.x * HT;
    const int d0 = blockIdx.y * ND;
    const int h  = h0 + ty;
    const long long cb = (long long)blockIdx.z * Dd * HW;

    const float* __restrict__ xr = x + cb + (long long)h * Wd + (tx << 2);
    float* __restrict__ orow = out + cb + (long long)d0 * HW
                                   + (long long)h * Wd + (tx << 2);
    const bool hm = (h > 0);
    const bool hp = (h < Hd - 1);

    const u64 c2   = pack2(2.f, 2.f);
    const u64 cm1  = pack2(-1.f, -1.f);
    const u64 eps2 = pack2(1e-6f, 1e-6f);

    // Load one plane's 3 rows (h-1,h,h+1), 4 w positions each.
    auto ld = [&](int p, float4& q0, float4& q1, float4& q2) {
        const float4 z = make_float4(0.f, 0.f, 0.f, 0.f);
        if ((unsigned)p >= (unsigned)Dd) { q0 = z; q1 = z; q2 = z; return; }
        const float* b = xr + (long long)p * HW;
        q0 = hm ? __ldg((const float4*)(b - Wd)) : z;
        q1 =      __ldg((const float4*)(b));
        q2 = hp ? __ldg((const float4*)(b + Wd)) : z;
    };

    // Row transform: gw (w-gradient) and sw (w-smooth), packed.
    auto row = [&](const float4& q, u64& gwl, u64& gwh, u64& swl, u64& swh) {
        float lf = __shfl_up_sync(0xffffffffu, q.w, 1);
        float rt = __shfl_down_sync(0xffffffffu, q.x, 1);
        if (tx == 0)  lf = 0.f;     // zero pad w = -1
        if (tx == 31) rt = 0.f;     // zero pad w = 128
        u64 ql = pack2(q.x, q.y);
        u64 qh = pack2(q.z, q.w);
        u64 s0 = pack2(lf,  q.x);   // (x[w-1]) for j=0,1
        u64 s1 = pack2(q.y, q.z);   // (x[w+1]) for j=0,1 == (x[w-1]) for j=2,3
        u64 s2 = pack2(q.w, rt);    // (x[w+1]) for j=2,3
        gwl = fma2(s0, cm1, s1);                 // x[w+1]-x[w-1]
        gwh = fma2(s1, cm1, s2);
        swl = fma2(ql, c2, add2(s0, s1));        // x[w-1]+2x[w]+x[w+1]
        swh = fma2(qh, c2, add2(s1, s2));
    };

    auto abc = [&](const float4& q0, const float4& q1, const float4& q2, ABC& o) {
        u64 g0l, g0h, s0l, s0h; row(q0, g0l, g0h, s0l, s0h);
        u64 g1l, g1h, s1l, s1h; row(q1, g1l, g1h, s1l, s1h);
        u64 g2l, g2h, s2l, s2h; row(q2, g2l, g2h, s2l, s2h);
        o.Al = fma2(g1l, c2, add2(g0l, g2l));
        o.Ah = fma2(g1h, c2, add2(g0h, g2h));
        o.Bl = fma2(s0l, cm1, s2l);
        o.Bh = fma2(s0h, cm1, s2h);
        o.Cl = fma2(s1l, c2, add2(s0l, s2l));
        o.Ch = fma2(s1h, c2, add2(s0h, s2h));
    };

    float4 P0, P1, P2, Q0, Q1, Q2;    // double-buffered plane rows
    ABC r;

    // State (packed): ed0/eh0 = partial for output t; ed1/eh1 = partial t+1;
    // Cp = C(t-1), Cq = C(t).
    u64 ed0l, ed0h, eh0l, eh0h, ed1l, ed1h, eh1l, eh1h, Cpl, Cph, Cql, Cqh;

    ld(d0 - 1, P0, P1, P2);
    ld(d0,     Q0, Q1, Q2);

    abc(P0, P1, P2, r);
    ed0l = r.Al; ed0h = r.Ah;
    eh0l = r.Bl; eh0h = r.Bh;
    Cpl  = r.Cl; Cph  = r.Ch;

    ld(d0 + 1, P0, P1, P2);           // prefetch plane d0+1
    abc(Q0, Q1, Q2, r);
    ed0l = fma2(r.Al, c2, ed0l); ed0h = fma2(r.Ah, c2, ed0h);
    eh0l = fma2(r.Bl, c2, eh0l); eh0h = fma2(r.Bh, c2, eh0h);
    ed1l = r.Al; ed1h = r.Ah;
    eh1l = r.Bl; eh1h = r.Bh;
    Cql  = r.Cl; Cqh  = r.Ch;

    #pragma unroll
    for (int i = 0; i < ND; ++i) {
        const int pn = (i < ND - 1) ? (d0 + i + 2) : Dd;   // Dd => zero-fill
        if (i & 1) { ld(pn, P0, P1, P2); abc(Q0, Q1, Q2, r); }
        else       { ld(pn, Q0, Q1, Q2); abc(P0, P1, P2, r); }

        u64 edl = add2(ed0l, r.Al), edh = add2(ed0h, r.Ah);
        u64 ehl = add2(eh0l, r.Bl), ehh = add2(eh0h, r.Bh);
        u64 ewl = fma2(Cpl, cm1, r.Cl), ewh = fma2(Cph, cm1, r.Ch);

        u64 ml = add2(fma2(ewl, ewl, fma2(ehl, ehl, mul2(edl, edl))), eps2);
        u64 mh = add2(fma2(ewh, ewh, fma2(ehh, ehh, mul2(edh, edh))), eps2);

        float m0, m1, m2, m3;
        unpack2(ml, m0, m1);
        unpack2(mh, m2, m3);
        float4 o4 = make_float4(m0 * rsqrtf_a(m0), m1 * rsqrtf_a(m1),
                                m2 * rsqrtf_a(m2), m3 * rsqrtf_a(m3));
        *(float4*)(orow + (long long)i * HW) = o4;

        ed0l = fma2(r.Al, c2, ed1l); ed0h = fma2(r.Ah, c2, ed1h);
        eh0l = fma2(r.Bl, c2, eh1l); eh0h = fma2(r.Bh, c2, eh1h);
        ed1l = r.Al; ed1h = r.Ah;
        eh1l = r.Bl; eh1h = r.Bh;
        Cpl = Cql; Cph = Cqh;
        Cql = r.Cl; Cqh = r.Ch;
    }
}

extern "C" void kernel_launch(void* const* d_in, const int* in_sizes, int n_in,
                              void* d_out, int out_size)
{
    const float* x = (const float*)d_in[0];
    float* out = (float*)d_out;
    dim3 grid(Hd / HT, Dd / ND, BCn);   // (16, 4, 32) = 2048 blocks
    dim3 block(32, 8);                  // 256 threads
    sobel3d_kernel<<<grid, block>>>(x, out);
}

// round 4
// speedup vs baseline: 1.2333x; 1.2333x over previous
#include <cuda_runtime.h>

// SobelEdge3D: out = sqrt(ed^2 + eh^2 + ew^2 + 1e-6), separable Sobel.
// Round-4: 2 h-rows per thread (row transforms + loads shared), scalar math,
// fused-eps fma chain, MUFU sqrt.approx, 32-bit offsets, d-plane double buffer.

constexpr int Wd  = 128;
constexpr int Hd  = 128;
constexpr int Dd  = 64;
constexpr int BCn = 32;          // B*C = 2*16
constexpr int HT  = 16;          // h rows per block (2 per thread-y)
constexpr int ND  = 16;          // d outputs per block
constexpr int HW  = Hd * Wd;

__device__ __forceinline__ float sqrt_approx(float v) {
    float r; asm("sqrt.approx.f32 %0,%1;" : "=f"(r) : "f"(v)); return r;
}

__global__ __launch_bounds__(256, 2)
void sobel3d_kernel(const float* __restrict__ x, float* __restrict__ out)
{
    const int tx = threadIdx.x;                 // 0..31 -> w = 4*tx..4*tx+3
    const int ty = threadIdx.y;                 // 0..7
    const int ha = blockIdx.x * HT + (ty << 1); // first of this thread's 2 h rows
    const int d0 = blockIdx.y * ND;

    const float* __restrict__ xb = x  + (size_t)blockIdx.z * (Dd * HW);
    float* __restrict__       ob = out + (size_t)blockIdx.z * (Dd * HW);

    const int rowbase = ha * Wd + (tx << 2);    // 32-bit element offset of row ha
    const bool hm = (ha > 0);                   // row ha-1 valid
    const bool hp = (ha + 2 < Hd);              // row ha+2 valid

    // Load one plane's 4 raw rows (ha-1, ha, ha+1, ha+2), 4 w each.
    auto ld = [&](int p, float4 (&R)[4]) {
        const float4 z = make_float4(0.f, 0.f, 0.f, 0.f);
        if ((unsigned)p >= (unsigned)Dd) { R[0]=z; R[1]=z; R[2]=z; R[3]=z; return; }
        const float* b = xb + p * HW + rowbase;
        R[0] = hm ? __ldg((const float4*)(b - Wd)) : z;
        R[1] =      __ldg((const float4*)(b));
        R[2] =      __ldg((const float4*)(b + Wd));       // ha+1 always valid
        R[3] = hp ? __ldg((const float4*)(b + 2 * Wd)) : z;
    };

    // Per-plane: row transforms (4 rows, shared) then A/B/C for 2 output rows.
    auto abc = [&](const float4 (&R)[4],
                   float (&A)[2][4], float (&B)[2][4], float (&C)[2][4]) {
        float g[4][4], s[4][4];
        #pragma unroll
        for (int r = 0; r < 4; ++r) {
            float4 q = R[r];
            float lf = __shfl_up_sync(0xffffffffu, q.w, 1);
            float rt = __shfl_down_sync(0xffffffffu, q.x, 1);
            if (tx == 0)  lf = 0.f;     // zero pad w = -1
            if (tx == 31) rt = 0.f;     // zero pad w = 128
            g[r][0] = q.y - lf;
            g[r][1] = q.z - q.x;
            g[r][2] = q.w - q.y;
            g[r][3] = rt  - q.z;
            s[r][0] = fmaf(2.f, q.x, lf  + q.y);
            s[r][1] = fmaf(2.f, q.y, q.x + q.z);
            s[r][2] = fmaf(2.f, q.z, q.y + q.w);
            s[r][3] = fmaf(2.f, q.w, q.z + rt);
        }
        #pragma unroll
        for (int o = 0; o < 2; ++o) {
            #pragma unroll
            for (int j = 0; j < 4; ++j) {
                A[o][j] = fmaf(2.f, g[o + 1][j], g[o][j] + g[o + 2][j]);
                B[o][j] = s[o + 2][j] - s[o][j];
                C[o][j] = fmaf(2.f, s[o + 1][j], s[o][j] + s[o + 2][j]);
            }
        }
    };

    float4 P[4], Q[4];
    float a[2][4], b[2][4], c[2][4];
    float ed0[2][4], eh0[2][4], ed1[2][4], eh1[2][4], Cp[2][4], Cq[2][4];

    // Prologue: planes d0-1 and d0.
    ld(d0 - 1, P);
    ld(d0,     Q);

    abc(P, a, b, c);
    #pragma unroll
    for (int o = 0; o < 2; ++o)
        #pragma unroll
        for (int j = 0; j < 4; ++j) {
            ed0[o][j] = a[o][j]; eh0[o][j] = b[o][j]; Cp[o][j] = c[o][j];
        }

    ld(d0 + 1, P);                    // prefetch plane d0+1
    abc(Q, a, b, c);
    #pragma unroll
    for (int o = 0; o < 2; ++o)
        #pragma unroll
        for (int j = 0; j < 4; ++j) {
            ed0[o][j] = fmaf(2.f, a[o][j], ed0[o][j]);
            eh0[o][j] = fmaf(2.f, b[o][j], eh0[o][j]);
            ed1[o][j] = a[o][j]; eh1[o][j] = b[o][j]; Cq[o][j] = c[o][j];
        }

    const int obase = d0 * HW + rowbase;

    // Steady state: buffer (i even ? P : Q) holds plane t+1; prefetch t+2.
    #pragma unroll
    for (int i = 0; i < ND; ++i) {
        const int pn = (i < ND - 1) ? (d0 + i + 2) : Dd;   // Dd => zero-fill
        if (i & 1) { ld(pn, P); abc(Q, a, b, c); }
        else       { ld(pn, Q); abc(P, a, b, c); }

        #pragma unroll
        for (int o = 0; o < 2; ++o) {
            float res[4];
            #pragma unroll
            for (int j = 0; j < 4; ++j) {
                float ed = ed0[o][j] + a[o][j];
                float eh = eh0[o][j] + b[o][j];
                float ew = c[o][j] - Cp[o][j];
                float m  = fmaf(ew, ew, fmaf(eh, eh, fmaf(ed, ed, 1e-6f)));
                res[j] = sqrt_approx(m);
                ed0[o][j] = fmaf(2.f, a[o][j], ed1[o][j]);
                eh0[o][j] = fmaf(2.f, b[o][j], eh1[o][j]);
                ed1[o][j] = a[o][j];
                eh1[o][j] = b[o][j];
                Cp[o][j]  = Cq[o][j];
                Cq[o][j]  = c[o][j];
            }
            *(float4*)(ob + obase + i * HW + o * Wd) =
                make_float4(res[0], res[1], res[2], res[3]);
        }
    }
}

extern "C" void kernel_launch(void* const* d_in, const int* in_sizes, int n_in,
                              void* d_out, int out_size)
{
    const float* x = (const float*)d_in[0];
    float* out = (float*)d_out;
    dim3 grid(Hd / HT, Dd / ND, BCn);   // (8, 4, 32) = 1024 blocks
    dim3 block(32, 8);                  // 256 threads, each: 4 w x 2 h x 16 d
    sobel3d_kernel<<<grid, block>>>(x, out);
}

// round 5
// speedup vs baseline: 1.4800x; 1.2000x over previous
#include <cuda_runtime.h>
#include <cstdint>

// SobelEdge3D: out = sqrt(ed^2 + eh^2 + ew^2 + 1e-6), separable Sobel.
// Round-5: cp.async smem ring (depth 3, private per-thread slots, no barriers)
// replaces register plane buffers -> fewer regs, 5 CTAs/SM, deep prefetch.
// Each thread: 4 w (float4) x 2 h rows x 16 d outputs.

constexpr int Wd  = 128;
constexpr int Hd  = 128;
constexpr int Dd  = 64;
constexpr int BCn = 32;          // B*C = 2*16
constexpr int HT  = 8;           // h rows per block (ty 0..3, 2 rows each)
constexpr int ND  = 16;          // d outputs per block
constexpr int HW  = Hd * Wd;
constexpr int NSLOT = 3;         // smem ring depth (planes in flight)

__device__ __forceinline__ float sqrt_approx(float v) {
    float r; asm("sqrt.approx.f32 %0,%1;" : "=f"(r) : "f"(v)); return r;
}
__device__ __forceinline__ void cp16(uint32_t dst, const float* src, int sz) {
    // 16B async copy; sz=0 => zero-fill (used for padding rows/planes).
    asm volatile("cp.async.ca.shared.global [%0], [%1], 16, %2;"
                 :: "r"(dst), "l"(src), "r"(sz));
}
__device__ __forceinline__ void cp_commit() {
    asm volatile("cp.async.commit_group;" ::: "memory");
}
__device__ __forceinline__ void cp_wait2() {
    asm volatile("cp.async.wait_group 2;" ::: "memory");
}

__global__ __launch_bounds__(128, 5)
void sobel3d_kernel(const float* __restrict__ x, float* __restrict__ out)
{
    // ring[slot][row][tid]: each thread's 4 rows of one plane, 16B each.
    __shared__ float4 ring[NSLOT][4][128];

    const int tid = threadIdx.x;
    const int tx  = tid & 31;                 // w = 4*tx .. 4*tx+3
    const int ty  = tid >> 5;                 // 0..3
    const int ha  = blockIdx.x * HT + (ty << 1);  // first of 2 output h rows
    const int d0  = blockIdx.y * ND;

    const float* __restrict__ xb = x   + (size_t)blockIdx.z * (Dd * HW);
    float* __restrict__       ob = out + (size_t)blockIdx.z * (Dd * HW);

    const uint32_t sb = (uint32_t)__cvta_generic_to_shared(ring) + tid * 16;

    // Issue one plane's 4 rows (ha-1..ha+2) as cp.async into a ring slot.
    auto cp_plane = [&](int p, int slot, bool use) {
        const int pc = min(max(p, 0), Dd - 1);                // clamped (addr safety)
        const bool pv = use && ((unsigned)p < (unsigned)Dd);
        const float* pb = xb + pc * HW + (tx << 2);
        const uint32_t d = sb + slot * (4 * 128 * 16);
        #pragma unroll
        for (int r = 0; r < 4; ++r) {
            const int hh = ha - 1 + r;
            const int hc = min(max(hh, 0), Hd - 1);
            const int sz = (pv && (unsigned)hh < (unsigned)Hd) ? 16 : 0;
            cp16(d + r * 2048, pb + hc * Wd, sz);
        }
        cp_commit();
    };

    // Per-plane: 4 row transforms from smem, fold to A/B/C for 2 output rows.
    auto abc = [&](int slot,
                   float (&A)[2][4], float (&B)[2][4], float (&C)[2][4]) {
        float g[4][4], s[4][4];
        #pragma unroll
        for (int r = 0; r < 4; ++r) {
            float4 q = ring[slot][r][tid];
            float lf = __shfl_up_sync(0xffffffffu, q.w, 1);
            float rt = __shfl_down_sync(0xffffffffu, q.x, 1);
            if (tx == 0)  lf = 0.f;     // zero pad w = -1
            if (tx == 31) rt = 0.f;     // zero pad w = 128
            g[r][0] = q.y - lf;
            g[r][1] = q.z - q.x;
            g[r][2] = q.w - q.y;
            g[r][3] = rt  - q.z;
            s[r][0] = fmaf(2.f, q.x, lf  + q.y);
            s[r][1] = fmaf(2.f, q.y, q.x + q.z);
            s[r][2] = fmaf(2.f, q.z, q.y + q.w);
            s[r][3] = fmaf(2.f, q.w, q.z + rt);
        }
        #pragma unroll
        for (int o = 0; o < 2; ++o) {
            #pragma unroll
            for (int j = 0; j < 4; ++j) {
                A[o][j] = fmaf(2.f, g[o + 1][j], g[o][j] + g[o + 2][j]);
                B[o][j] = s[o + 2][j] - s[o][j];
                C[o][j] = fmaf(2.f, s[o + 1][j], s[o][j] + s[o + 2][j]);
            }
        }
    };

    float a[2][4], b[2][4], c[2][4];
    float ed0[2][4], eh0[2][4], ed1[2][4], eh1[2][4], Cp[2][4], Cq[2][4];

    // Prologue: launch planes d0-1, d0, d0+1 (3 groups in flight).
    cp_plane(d0 - 1, 0, true);
    cp_plane(d0,     1, true);
    cp_plane(d0 + 1, 2, true);

    // Consume plane d0-1, refill slot 0 with plane d0+2.
    cp_wait2();
    abc(0, a, b, c);
    #pragma unroll
    for (int o = 0; o < 2; ++o)
        #pragma unroll
        for (int j = 0; j < 4; ++j) {
            ed0[o][j] = a[o][j]; eh0[o][j] = b[o][j]; Cp[o][j] = c[o][j];
        }
    cp_plane(d0 + 2, 0, true);

    // Consume plane d0, refill slot 1 with plane d0+3.
    cp_wait2();
    abc(1, a, b, c);
    #pragma unroll
    for (int o = 0; o < 2; ++o)
        #pragma unroll
        for (int j = 0; j < 4; ++j) {
            ed0[o][j] = fmaf(2.f, a[o][j], ed0[o][j]);
            eh0[o][j] = fmaf(2.f, b[o][j], eh0[o][j]);
            ed1[o][j] = a[o][j]; eh1[o][j] = b[o][j]; Cq[o][j] = c[o][j];
        }
    cp_plane(d0 + 3, 1, true);

    const int obase = d0 * HW + ha * Wd + (tx << 2);

    // Steady state: iter i consumes plane d0+1+i (slot (i+2)%3), emits output
    // d0+i, refills the just-read slot with plane d0+i+4 (dummy past d0+ND).
    #pragma unroll
    for (int i = 0; i < ND; ++i) {
        const int slot = (i + 2) % 3;
        cp_wait2();
        abc(slot, a, b, c);

        #pragma unroll
        for (int o = 0; o < 2; ++o) {
            float res[4];
            #pragma unroll
            for (int j = 0; j < 4; ++j) {
                float ed = ed0[o][j] + a[o][j];
                float eh = eh0[o][j] + b[o][j];
                float ew = c[o][j] - Cp[o][j];
                float m  = fmaf(ew, ew, fmaf(eh, eh, fmaf(ed, ed, 1e-6f)));
                res[j] = sqrt_approx(m);
                ed0[o][j] = fmaf(2.f, a[o][j], ed1[o][j]);
                eh0[o][j] = fmaf(2.f, b[o][j], eh1[o][j]);
                ed1[o][j] = a[o][j];
                eh1[o][j] = b[o][j];
                Cp[o][j]  = Cq[o][j];
                Cq[o][j]  = c[o][j];
            }
            *(float4*)(ob + obase + i * HW + o * Wd) =
                make_float4(res[0], res[1], res[2], res[3]);
        }

        // Refill: plane d0+i+4 is needed only if <= d0+ND; otherwise dummy
        // (sz=0) cp group to keep wait_group accounting uniform.
        cp_plane(d0 + i + 4, slot, (i + 4) <= ND);
    }
}

extern "C" void kernel_launch(void* const* d_in, const int* in_sizes, int n_in,
                              void* d_out, int out_size)
{
    const float* x = (const float*)d_in[0];
    float* out = (float*)d_out;
    dim3 grid(Hd / HT, Dd / ND, BCn);   // (16, 4, 32) = 2048 blocks
    dim3 block(128);                    // 4 warps; thread = 4w x 2h x 16d
    sobel3d_kernel<<<grid, block>>>(x, out);
}